// round 15
// baseline (speedup 1.0000x reference)
#include <cuda_runtime.h>
#include <cuda_fp16.h>
#include <cstdint>

#define D_VOCAB 262
#define D_EMB   128
#define NTAP    5
#define CW      16
#define NSEQ    32768
#define NCHUNK  74
#define THREADS 512
#define NCTAS   (NCHUNK * 2)            // 148
// smem: table region [NTAP*D_VOCAB] rows of 64 ch (8 x uint4) = 167,680 B
#define SMEM_BYTES (NTAP * D_VOCAB * 32 * 4)
// uint4-unit stride of one tap plane: 262 rows * 8 uint4
#define TAPSTRIDE16 (D_VOCAB * 8)
// phase-1 weight scratch: ws[i][k*32+eL], row stride 164 floats (83,968 B)
#define WROW 164
// phase-1 emb scratch right after ws: 8 rows x 128 floats (4 KB)
#define EMB_OFF (D_EMB * WROW)

// fp16 contrib table: [tap][vocab][emb]
__device__ __align__(16) __half g_tab[NTAP * D_VOCAB * D_EMB];
// narrowed ids, PRE-MULTIPLIED BY 8 (uint4 row index); written phase 1,
// read phase 2 with PLAIN coherent loads only (__ldg illegal: same-launch).
__device__ __align__(16) unsigned short g_ids16[NSEQ * CW];
// grid-wide ticket barrier (monotonic across graph replays; no reset needed)
__device__ unsigned g_bar;

// ---------------------------------------------------------------------------
__device__ __forceinline__ uint4 h2add4(uint4 a, uint4 b) {
    uint4 r;
    *(__half2*)&r.x = __hadd2(*(const __half2*)&a.x, *(const __half2*)&b.x);
    *(__half2*)&r.y = __hadd2(*(const __half2*)&a.y, *(const __half2*)&b.y);
    *(__half2*)&r.z = __hadd2(*(const __half2*)&a.z, *(const __half2*)&b.z);
    *(__half2*)&r.w = __hadd2(*(const __half2*)&a.w, *(const __half2*)&b.w);
    return r;
}
__device__ __forceinline__ uint4 h2max4(uint4 a, uint4 b) {
    uint4 r;
    *(__half2*)&r.x = __hmax2(*(const __half2*)&a.x, *(const __half2*)&b.x);
    *(__half2*)&r.y = __hmax2(*(const __half2*)&a.y, *(const __half2*)&b.y);
    *(__half2*)&r.z = __hmax2(*(const __half2*)&a.z, *(const __half2*)&b.z);
    *(__half2*)&r.w = __hmax2(*(const __half2*)&a.w, *(const __half2*)&b.w);
    return r;
}

// Select 32-bit word holding ids 2j, 2j+1 (t compile-time const -> folds).
#define RAWW(t) ( ((t)>>1)==0 ? raw2[0].x : ((t)>>1)==1 ? raw2[0].y : \
                  ((t)>>1)==2 ? raw2[0].z : ((t)>>1)==3 ? raw2[0].w : \
                  ((t)>>1)==4 ? raw2[1].x : ((t)>>1)==5 ? raw2[1].y : \
                  ((t)>>1)==6 ? raw2[1].z : raw2[1].w )

// One sequence-group iteration at n0: gathers via ACUR, JIT-unpacks the NEXT
// iteration's indices into ANXT (2 instr per t, interleaved with LDS so the
// crossbar never drains), then prefetches the following ids and stores out.
#define ITER_BODY(ACUR, ANXT)                                                \
{                                                                            \
    const int nsel = n0 + q;                                                 \
    uint4 sb[2][NTAP];                                                       \
    _Pragma("unroll")                                                        \
    for (int k = 2; k < NTAP; ++k)                                           \
        sb[0][k] = s_tab16[k * TAPSTRIDE16 + ACUR[k - 2]];                   \
    uint4 me, mo;                                                            \
    _Pragma("unroll")                                                        \
    for (int t = 0; t < CW; ++t) {                                           \
        const int cur = t & 1, nxt = cur ^ 1;                                \
        { unsigned w = RAWW(t);                                              \
          ANXT[t] = (int)((t & 1) ? (w >> 16) : (w & 0xFFFFu)) + l7; }       \
        if (t + 1 < CW) {                                                    \
            const int tn = t + 1;                                            \
            const int klo_n = (tn < 2) ? (2 - tn) : 0;                       \
            const int khi_n = (tn > CW - 3) ? (CW + 1 - tn) : NTAP - 1;      \
            _Pragma("unroll")                                                \
            for (int k = 0; k < NTAP; ++k) {                                 \
                if (k < klo_n || k > khi_n) continue;                        \
                sb[nxt][k] = s_tab16[k * TAPSTRIDE16 + ACUR[tn + k - 2]];    \
            }                                                                \
        }                                                                    \
        const int klo = (t < 2) ? (2 - t) : 0;                               \
        const int khi = (t > CW - 3) ? (CW + 1 - t) : NTAP - 1;              \
        const int nv = khi - klo + 1;                                        \
        uint4 y;                                                             \
        if (nv == 5) {                                                       \
            y = h2add4(h2add4(h2add4(sb[cur][0], sb[cur][1]),                \
                              h2add4(sb[cur][2], sb[cur][3])), sb[cur][4]);  \
        } else if (nv == 4) {                                                \
            y = h2add4(h2add4(sb[cur][klo], sb[cur][klo + 1]),               \
                       h2add4(sb[cur][klo + 2], sb[cur][klo + 3]));          \
        } else {                                                             \
            y = h2add4(h2add4(sb[cur][klo], sb[cur][klo + 1]),               \
                       sb[cur][klo + 2]);                                    \
        }                                                                    \
        if (t == 0)      me = y;                                             \
        else if (t == 1) mo = y;                                             \
        else if ((t & 1) == 0) me = h2max4(me, y);                           \
        else                   mo = h2max4(mo, y);                           \
    }                                                                        \
    /* prefetch ids for n0 + 2*step (raw2 fully consumed into ANXT) */       \
    {                                                                        \
        const int nn = n0 + 2 * step + q;                                    \
        const int nc = min(nn < end ? nn : (end - 1), end - 1);              \
        const uint4* p = (const uint4*)(g_ids16 + (size_t)nc * CW);          \
        raw2[0] = p[0];                                                      \
        raw2[1] = p[1];                                                      \
    }                                                                        \
    const uint4 m = h2max4(me, mo);                                          \
    if (nsel < end) {                                                        \
        const float4 bias0 = __ldg((const float4*)(conv_b + g*64 + l7*8));   \
        const float4 bias1 = __ldg((const float4*)(conv_b + g*64 + l7*8+4)); \
        float2 c0 = __half22float2(*(const __half2*)&m.x);                   \
        float2 c1 = __half22float2(*(const __half2*)&m.y);                   \
        float2 c2 = __half22float2(*(const __half2*)&m.z);                   \
        float2 c3 = __half22float2(*(const __half2*)&m.w);                   \
        float4 o0, o1;                                                       \
        o0.x = c0.x + bias0.x; o0.y = c0.y + bias0.y;                        \
        o0.z = c1.x + bias0.z; o0.w = c1.y + bias0.w;                        \
        o1.x = c2.x + bias1.x; o1.y = c2.y + bias1.y;                        \
        o1.z = c3.x + bias1.z; o1.w = c3.y + bias1.w;                        \
        float* op = out + (size_t)nsel * D_EMB + g * 64 + l7 * 8;            \
        *(float4*)op = o0;                                                   \
        *(float4*)(op + 4) = o1;                                             \
    }                                                                        \
}

// ---------------------------------------------------------------------------
// Fused kernel. Grid (74, 2) = 148 CTAs, 164 KB smem -> 1 CTA/SM, all
// co-resident -> device-wide ticket barrier is safe.
// ---------------------------------------------------------------------------
__global__ void __launch_bounds__(THREADS, 1)
conv_char_fused(const int* __restrict__ ids_raw,
                const float* __restrict__ emb,
                const float* __restrict__ conv_w,
                const float* __restrict__ conv_b,
                float* __restrict__ out) {
    extern __shared__ uint4 s_tab16[];
    float* ws = (float*)s_tab16;                 // phase-1 alias (88 KB)
    const int g = blockIdx.y;
    const int lane = threadIdx.x & 31;
    const int warp = threadIdx.x >> 5;
    const int l7 = lane & 7;
    const int q = lane >> 3;
    const int cta = blockIdx.y * NCHUNK + blockIdx.x;   // 0..147

    // Per-warp int64-vs-int32 detection (int64 ids < 262 -> zero high words).
    int s2;
    {
        int v = ids_raw[2 * lane + 1] | ids_raw[64 + 2 * lane + 1];
        s2 = (__ballot_sync(0xffffffffu, v != 0) == 0u) ? 1 : 0;
    }

    // ===== Phase 1a: build this CTA's slice of g_tab ======================
    {
        const int eg = cta & 3;            // 32-e group
        const int vg = cta >> 2;           // 8-v group (>=33 -> idle)
        const int e0 = eg * 32;
        const int v0 = vg * 8;

        const float4* __restrict__ cw4 = (const float4*)conv_w;
        for (int idx = threadIdx.x; idx < 32 * 160; idx += THREADS) {
            const int r = idx / 160;
            const int c = idx % 160;
            float4 w = __ldg(&cw4[(size_t)(e0 + r) * 160 + c]);
            const int j = 4 * c;
            ws[((j + 0) / 5) * WROW + ((j + 0) % 5) * 32 + r] = w.x;
            ws[((j + 1) / 5) * WROW + ((j + 1) % 5) * 32 + r] = w.y;
            ws[((j + 2) / 5) * WROW + ((j + 2) % 5) * 32 + r] = w.z;
            ws[((j + 3) / 5) * WROW + ((j + 3) % 5) * 32 + r] = w.w;
        }
        {
            const float4* __restrict__ embg = (const float4*)emb;
            float4* se4 = (float4*)(ws + EMB_OFF);
            if (threadIdx.x < 256) {
                const int vr = threadIdx.x >> 5;     // 0..7
                const int c = threadIdx.x & 31;
                const int vv = v0 + vr;
                se4[threadIdx.x] = (vv < D_VOCAB)
                    ? __ldg(&embg[vv * 32 + c])
                    : make_float4(0.f, 0.f, 0.f, 0.f);
            }
        }
        __syncthreads();

        if (threadIdx.x < 320 && v0 < D_VOCAB) {
            const int vh = threadIdx.x / 160;          // 0..1
            const int k = (threadIdx.x % 160) >> 5;    // 0..4
            const int eL = threadIdx.x & 31;
            const float* __restrict__ wcol = ws + k * 32 + eL;
            const float4* __restrict__ se4 = (const float4*)(ws + EMB_OFF);
            const int vb = vh * 4;

            float acc[4];
            #pragma unroll
            for (int v = 0; v < 4; ++v) acc[v] = 0.f;

            #pragma unroll 4
            for (int i4 = 0; i4 < 32; ++i4) {
                const float w0 = wcol[(i4 * 4 + 0) * WROW];
                const float w1 = wcol[(i4 * 4 + 1) * WROW];
                const float w2 = wcol[(i4 * 4 + 2) * WROW];
                const float w3 = wcol[(i4 * 4 + 3) * WROW];
                #pragma unroll
                for (int v = 0; v < 4; ++v) {
                    float4 em = se4[(vb + v) * 32 + i4];
                    acc[v] = fmaf(em.x, w0, acc[v]);
                    acc[v] = fmaf(em.y, w1, acc[v]);
                    acc[v] = fmaf(em.z, w2, acc[v]);
                    acc[v] = fmaf(em.w, w3, acc[v]);
                }
            }
            #pragma unroll
            for (int v = 0; v < 4; ++v) {
                const int vv = v0 + vb + v;
                if (vv < D_VOCAB)
                    g_tab[(k * D_VOCAB + vv) * D_EMB + e0 + eL] =
                        __float2half(acc[v]);
            }
        }
    }

    // ===== Phase 1b: narrow ids to int16, PRE-MULTIPLIED BY 8 =============
    {
        const int stride = NCTAS * THREADS;
        int i = cta * THREADS + threadIdx.x;
        if (s2) {
            const uint2* __restrict__ p2 = (const uint2*)ids_raw;
            for (; i < NSEQ * CW; i += stride)
                g_ids16[i] = (unsigned short)(__ldg(&p2[i]).x * 8u);
        } else {
            for (; i < NSEQ * CW; i += stride)
                g_ids16[i] = (unsigned short)(__ldg(&ids_raw[i]) * 8);
        }
    }

    // Release all stores, then grid barrier.
    __threadfence();
    __syncthreads();
    if (threadIdx.x == 0) {
        unsigned t = atomicAdd(&g_bar, 1u);
        unsigned target = (t / (unsigned)NCTAS) * (unsigned)NCTAS
                          + (unsigned)NCTAS;
        while (*(volatile unsigned*)&g_bar < target) { }
        __threadfence();
    }
    __syncthreads();

    // ===== Phase 2: main loop =============================================
    const int chunk = (NSEQ + NCHUNK - 1) / NCHUNK;  // 443
    const int base = blockIdx.x * chunk;
    const int end = min(base + chunk, NSEQ);
    const int step = 4 * (THREADS / 32);             // 64

    // Prefetch iteration-0 ids (plain coherent loads; L2-hot).
    uint4 raw2[2];
    {
        const int nc = min(base + 4 * warp + q, end - 1);
        const uint4* p = (const uint4*)(g_ids16 + (size_t)nc * CW);
        raw2[0] = p[0];
        raw2[1] = p[1];
    }

    // Stage table slice from hot L2 (coalesced; plain loads).
    {
        const char* gb = (const char*)g_tab;
        for (int idx = threadIdx.x; idx < NTAP * D_VOCAB * 8; idx += THREADS) {
            int r = idx >> 3, c = idx & 7;
            s_tab16[idx] = *(const uint4*)(gb + (size_t)r * 256 + g * 128 + c * 16);
        }
    }
    __syncthreads();

    // Block-unpack iteration-0 ids, then prefetch iteration-1 ids.
    int a[CW], an[CW];
    {
        #pragma unroll
        for (int t = 0; t < CW; ++t) {
            unsigned w = RAWW(t);
            a[t] = (int)((t & 1) ? (w >> 16) : (w & 0xFFFFu)) + l7;
        }
        const int nn = base + 4 * warp + step + q;
        const int nc = min(nn < end ? nn : (end - 1), end - 1);
        const uint4* p = (const uint4*)(g_ids16 + (size_t)nc * CW);
        raw2[0] = p[0];
        raw2[1] = p[1];
    }

    int n0 = base + 4 * warp;
    while (n0 < end) {
        ITER_BODY(a, an)
        n0 += step;
        if (n0 >= end) break;
        ITER_BODY(an, a)
        n0 += step;
    }
}

// ---------------------------------------------------------------------------
extern "C" void kernel_launch(void* const* d_in, const int* in_sizes, int n_in,
                              void* d_out, int out_size) {
    const int* input = nullptr;
    const float* emb = nullptr;
    const float* conv_w = nullptr;
    const float* conv_b = nullptr;
    for (int i = 0; i < n_in; ++i) {
        switch (in_sizes[i]) {
            case 524288: input  = (const int*)d_in[i];   break;  // ids [128,256,16]
            case 33536:  emb    = (const float*)d_in[i]; break;  // [262,128]
            case 81920:  conv_w = (const float*)d_in[i]; break;  // [128,128,5]
            case 128:    conv_b = (const float*)d_in[i]; break;  // [128]
            default: break;  // lengths (32768) unused
        }
    }

    cudaFuncSetAttribute(conv_char_fused,
                         cudaFuncAttributeMaxDynamicSharedMemorySize, SMEM_BYTES);
    conv_char_fused<<<dim3(NCHUNK, 2), THREADS, SMEM_BYTES>>>(
        input, emb, conv_w, conv_b, (float*)d_out);
}

// round 16
// speedup vs baseline: 1.0531x; 1.0531x over previous
#include <cuda_runtime.h>
#include <cuda_fp16.h>
#include <cstdint>

#define D_VOCAB 262
#define D_EMB   128
#define NTAP    5
#define CW      16
#define NSEQ    32768
#define NCHUNK  74
#define THREADS 512
#define NCTAS   (NCHUNK * 2)            // 148
// smem: table region [NTAP*D_VOCAB] rows of 64 ch (8 x uint4) = 167,680 B
#define SMEM_BYTES (NTAP * D_VOCAB * 32 * 4)
// uint4-unit stride of one tap plane: 262 rows * 8 uint4
#define TAPSTRIDE16 (D_VOCAB * 8)
// phase-1 weight scratch: ws[i][k*32+eL], row stride 164 floats (83,968 B)
#define WROW 164
// phase-1 emb scratch right after ws: 8 rows x 128 floats (4 KB)
#define EMB_OFF (D_EMB * WROW)

// fp16 contrib table: [tap][vocab][emb]
__device__ __align__(16) __half g_tab[NTAP * D_VOCAB * D_EMB];
// narrowed ids, PRE-MULTIPLIED BY 8 (uint4 row index); written phase 1,
// read phase 2 with PLAIN coherent loads only (__ldg illegal: same-launch).
__device__ __align__(16) unsigned short g_ids16[NSEQ * CW];
// grid-wide ticket barrier (monotonic across graph replays; no reset needed)
__device__ unsigned g_bar;

// ---------------------------------------------------------------------------
__device__ __forceinline__ uint4 h2add4(uint4 a, uint4 b) {
    uint4 r;
    *(__half2*)&r.x = __hadd2(*(const __half2*)&a.x, *(const __half2*)&b.x);
    *(__half2*)&r.y = __hadd2(*(const __half2*)&a.y, *(const __half2*)&b.y);
    *(__half2*)&r.z = __hadd2(*(const __half2*)&a.z, *(const __half2*)&b.z);
    *(__half2*)&r.w = __hadd2(*(const __half2*)&a.w, *(const __half2*)&b.w);
    return r;
}
__device__ __forceinline__ uint4 h2max4(uint4 a, uint4 b) {
    uint4 r;
    *(__half2*)&r.x = __hmax2(*(const __half2*)&a.x, *(const __half2*)&b.x);
    *(__half2*)&r.y = __hmax2(*(const __half2*)&a.y, *(const __half2*)&b.y);
    *(__half2*)&r.z = __hmax2(*(const __half2*)&a.z, *(const __half2*)&b.z);
    *(__half2*)&r.w = __hmax2(*(const __half2*)&a.w, *(const __half2*)&b.w);
    return r;
}

// ---------------------------------------------------------------------------
// Fused kernel. Grid (74, 2) = 148 CTAs, 164 KB smem -> 1 CTA/SM, all
// co-resident -> device-wide ticket barrier is safe.
// Phase 2 processes EIGHT sequences per warp-iteration (two quarter-warp
// groups A/B fused): 148 gather-LDS per iteration with one shared
// unpack/prefetch/epilogue block -> half the no-LDS boundary windows, and
// B's gathers are independent of A's adds (dual-chain ILP).
// ---------------------------------------------------------------------------
__global__ void __launch_bounds__(THREADS, 1)
conv_char_fused(const int* __restrict__ ids_raw,
                const float* __restrict__ emb,
                const float* __restrict__ conv_w,
                const float* __restrict__ conv_b,
                float* __restrict__ out) {
    extern __shared__ uint4 s_tab16[];
    float* ws = (float*)s_tab16;                 // phase-1 alias (88 KB)
    const int g = blockIdx.y;
    const int lane = threadIdx.x & 31;
    const int warp = threadIdx.x >> 5;
    const int l7 = lane & 7;
    const int q = lane >> 3;
    const int cta = blockIdx.y * NCHUNK + blockIdx.x;   // 0..147

    // Per-warp int64-vs-int32 detection (int64 ids < 262 -> zero high words).
    int s2;
    {
        int v = ids_raw[2 * lane + 1] | ids_raw[64 + 2 * lane + 1];
        s2 = (__ballot_sync(0xffffffffu, v != 0) == 0u) ? 1 : 0;
    }

    // ===== Phase 1a: build this CTA's slice of g_tab ======================
    {
        const int eg = cta & 3;            // 32-e group
        const int vg = cta >> 2;           // 8-v group (>=33 -> idle)
        const int e0 = eg * 32;
        const int v0 = vg * 8;

        const float4* __restrict__ cw4 = (const float4*)conv_w;
        for (int idx = threadIdx.x; idx < 32 * 160; idx += THREADS) {
            const int r = idx / 160;
            const int c = idx % 160;
            float4 w = __ldg(&cw4[(size_t)(e0 + r) * 160 + c]);
            const int j = 4 * c;
            ws[((j + 0) / 5) * WROW + ((j + 0) % 5) * 32 + r] = w.x;
            ws[((j + 1) / 5) * WROW + ((j + 1) % 5) * 32 + r] = w.y;
            ws[((j + 2) / 5) * WROW + ((j + 2) % 5) * 32 + r] = w.z;
            ws[((j + 3) / 5) * WROW + ((j + 3) % 5) * 32 + r] = w.w;
        }
        {
            const float4* __restrict__ embg = (const float4*)emb;
            float4* se4 = (float4*)(ws + EMB_OFF);
            if (threadIdx.x < 256) {
                const int vr = threadIdx.x >> 5;     // 0..7
                const int c = threadIdx.x & 31;
                const int vv = v0 + vr;
                se4[threadIdx.x] = (vv < D_VOCAB)
                    ? __ldg(&embg[vv * 32 + c])
                    : make_float4(0.f, 0.f, 0.f, 0.f);
            }
        }
        __syncthreads();

        if (threadIdx.x < 320 && v0 < D_VOCAB) {
            const int vh = threadIdx.x / 160;          // 0..1
            const int k = (threadIdx.x % 160) >> 5;    // 0..4
            const int eL = threadIdx.x & 31;
            const float* __restrict__ wcol = ws + k * 32 + eL;
            const float4* __restrict__ se4 = (const float4*)(ws + EMB_OFF);
            const int vb = vh * 4;

            float acc[4];
            #pragma unroll
            for (int v = 0; v < 4; ++v) acc[v] = 0.f;

            #pragma unroll 4
            for (int i4 = 0; i4 < 32; ++i4) {
                const float w0 = wcol[(i4 * 4 + 0) * WROW];
                const float w1 = wcol[(i4 * 4 + 1) * WROW];
                const float w2 = wcol[(i4 * 4 + 2) * WROW];
                const float w3 = wcol[(i4 * 4 + 3) * WROW];
                #pragma unroll
                for (int v = 0; v < 4; ++v) {
                    float4 em = se4[(vb + v) * 32 + i4];
                    acc[v] = fmaf(em.x, w0, acc[v]);
                    acc[v] = fmaf(em.y, w1, acc[v]);
                    acc[v] = fmaf(em.z, w2, acc[v]);
                    acc[v] = fmaf(em.w, w3, acc[v]);
                }
            }
            #pragma unroll
            for (int v = 0; v < 4; ++v) {
                const int vv = v0 + vb + v;
                if (vv < D_VOCAB)
                    g_tab[(k * D_VOCAB + vv) * D_EMB + e0 + eL] =
                        __float2half(acc[v]);
            }
        }
    }

    // ===== Phase 1b: narrow ids to int16, PRE-MULTIPLIED BY 8 =============
    {
        const int stride = NCTAS * THREADS;
        int i = cta * THREADS + threadIdx.x;
        if (s2) {
            const uint2* __restrict__ p2 = (const uint2*)ids_raw;
            for (; i < NSEQ * CW; i += stride)
                g_ids16[i] = (unsigned short)(__ldg(&p2[i]).x * 8u);
        } else {
            for (; i < NSEQ * CW; i += stride)
                g_ids16[i] = (unsigned short)(__ldg(&ids_raw[i]) * 8);
        }
    }

    // Release all stores, then grid barrier.
    __threadfence();
    __syncthreads();
    if (threadIdx.x == 0) {
        unsigned t = atomicAdd(&g_bar, 1u);
        unsigned target = (t / (unsigned)NCTAS) * (unsigned)NCTAS
                          + (unsigned)NCTAS;
        while (*(volatile unsigned*)&g_bar < target) { }
        __threadfence();
    }
    __syncthreads();

    // ===== Phase 2: main loop, 8 seqs per warp-iteration ==================
    const int chunk = (NSEQ + NCHUNK - 1) / NCHUNK;  // 443
    const int base = blockIdx.x * chunk;
    const int end = min(base + chunk, NSEQ);
    const int step = 8 * (THREADS / 32);             // 128

    // Prefetch iteration-0 ids for both groups (plain coherent loads).
    uint4 rawA[2], rawB[2];
    {
        const int ncA = min(base + 8 * warp + q, end - 1);
        const int ncB = min(base + 8 * warp + 4 + q, end - 1);
        const uint4* pA = (const uint4*)(g_ids16 + (size_t)ncA * CW);
        const uint4* pB = (const uint4*)(g_ids16 + (size_t)ncB * CW);
        rawA[0] = pA[0]; rawA[1] = pA[1];
        rawB[0] = pB[0]; rawB[1] = pB[1];
    }

    // Stage table slice from hot L2 (coalesced; plain loads).
    {
        const char* gb = (const char*)g_tab;
        for (int idx = threadIdx.x; idx < NTAP * D_VOCAB * 8; idx += THREADS) {
            int r = idx >> 3, c = idx & 7;
            s_tab16[idx] = *(const uint4*)(gb + (size_t)r * 256 + g * 128 + c * 16);
        }
    }
    __syncthreads();

    for (int n0 = base + 8 * warp; n0 < end; n0 += step) {
        const int nselA = n0 + q;
        const int nselB = n0 + 4 + q;

        // Unpack 32 ids (pre-multiplied by 8) -> gather indices.
        int aA[CW], aB[CW];
        {
            const unsigned* wA = (const unsigned*)rawA;
            const unsigned* wB = (const unsigned*)rawB;
            #pragma unroll
            for (int j = 0; j < 8; ++j) {
                unsigned a = wA[j], b = wB[j];
                aA[2 * j]     = (int)(a & 0xFFFFu) + l7;
                aA[2 * j + 1] = (int)(a >> 16) + l7;
                aB[2 * j]     = (int)(b & 0xFFFFu) + l7;
                aB[2 * j + 1] = (int)(b >> 16) + l7;
            }
        }

        // Prefetch next iteration's ids (plain loads); hides under t-loop.
        {
            const int nnA = n0 + step + q;
            const int nnB = n0 + step + 4 + q;
            const int ncA = min(nnA < end ? nnA : (end - 1), end - 1);
            const int ncB = min(nnB < end ? nnB : (end - 1), end - 1);
            const uint4* pA = (const uint4*)(g_ids16 + (size_t)ncA * CW);
            const uint4* pB = (const uint4*)(g_ids16 + (size_t)ncB * CW);
            rawA[0] = pA[0]; rawA[1] = pA[1];
            rawB[0] = pB[0]; rawB[1] = pB[1];
        }

        // Interleaved dual-group t-loop: B's gathers independent of A's adds.
        uint4 meA, moA, meB, moB;
        #pragma unroll
        for (int t = 0; t < CW; ++t) {
            const int klo = (t < 2) ? (2 - t) : 0;
            const int khi = (t > CW - 3) ? (CW + 1 - t) : NTAP - 1;
            const int nv = khi - klo + 1;

            uint4 sA[NTAP], sB[NTAP];
            #pragma unroll
            for (int k = 0; k < NTAP; ++k) {
                if (k < klo || k > khi) continue;
                sA[k] = s_tab16[k * TAPSTRIDE16 + aA[t + k - 2]];
                sB[k] = s_tab16[k * TAPSTRIDE16 + aB[t + k - 2]];
            }

            uint4 yA, yB;
            if (nv == 5) {
                yA = h2add4(h2add4(h2add4(sA[0], sA[1]), h2add4(sA[2], sA[3])), sA[4]);
                yB = h2add4(h2add4(h2add4(sB[0], sB[1]), h2add4(sB[2], sB[3])), sB[4]);
            } else if (nv == 4) {
                yA = h2add4(h2add4(sA[klo], sA[klo + 1]), h2add4(sA[klo + 2], sA[klo + 3]));
                yB = h2add4(h2add4(sB[klo], sB[klo + 1]), h2add4(sB[klo + 2], sB[klo + 3]));
            } else {
                yA = h2add4(h2add4(sA[klo], sA[klo + 1]), sA[klo + 2]);
                yB = h2add4(h2add4(sB[klo], sB[klo + 1]), sB[klo + 2]);
            }

            if (t == 0)      { meA = yA; meB = yB; }
            else if (t == 1) { moA = yA; moB = yB; }
            else if ((t & 1) == 0) { meA = h2max4(meA, yA); meB = h2max4(meB, yB); }
            else                   { moA = h2max4(moA, yA); moB = h2max4(moB, yB); }
        }
        const uint4 mA = h2max4(meA, moA);
        const uint4 mB = h2max4(meB, moB);

        const float4 bias0 = __ldg((const float4*)(conv_b + g * 64 + l7 * 8));
        const float4 bias1 = __ldg((const float4*)(conv_b + g * 64 + l7 * 8 + 4));

        if (nselA < end) {
            float2 c0 = __half22float2(*(const __half2*)&mA.x);
            float2 c1 = __half22float2(*(const __half2*)&mA.y);
            float2 c2 = __half22float2(*(const __half2*)&mA.z);
            float2 c3 = __half22float2(*(const __half2*)&mA.w);
            float4 o0, o1;
            o0.x = c0.x + bias0.x; o0.y = c0.y + bias0.y;
            o0.z = c1.x + bias0.z; o0.w = c1.y + bias0.w;
            o1.x = c2.x + bias1.x; o1.y = c2.y + bias1.y;
            o1.z = c3.x + bias1.z; o1.w = c3.y + bias1.w;
            float* op = out + (size_t)nselA * D_EMB + g * 64 + l7 * 8;
            *(float4*)op = o0;
            *(float4*)(op + 4) = o1;
        }
        if (nselB < end) {
            float2 c0 = __half22float2(*(const __half2*)&mB.x);
            float2 c1 = __half22float2(*(const __half2*)&mB.y);
            float2 c2 = __half22float2(*(const __half2*)&mB.z);
            float2 c3 = __half22float2(*(const __half2*)&mB.w);
            float4 o0, o1;
            o0.x = c0.x + bias0.x; o0.y = c0.y + bias0.y;
            o0.z = c1.x + bias0.z; o0.w = c1.y + bias0.w;
            o1.x = c2.x + bias1.x; o1.y = c2.y + bias1.y;
            o1.z = c3.x + bias1.z; o1.w = c3.y + bias1.w;
            float* op = out + (size_t)nselB * D_EMB + g * 64 + l7 * 8;
            *(float4*)op = o0;
            *(float4*)(op + 4) = o1;
        }
    }
}

// ---------------------------------------------------------------------------
extern "C" void kernel_launch(void* const* d_in, const int* in_sizes, int n_in,
                              void* d_out, int out_size) {
    const int* input = nullptr;
    const float* emb = nullptr;
    const float* conv_w = nullptr;
    const float* conv_b = nullptr;
    for (int i = 0; i < n_in; ++i) {
        switch (in_sizes[i]) {
            case 524288: input  = (const int*)d_in[i];   break;  // ids [128,256,16]
            case 33536:  emb    = (const float*)d_in[i]; break;  // [262,128]
            case 81920:  conv_w = (const float*)d_in[i]; break;  // [128,128,5]
            case 128:    conv_b = (const float*)d_in[i]; break;  // [128]
            default: break;  // lengths (32768) unused
        }
    }

    cudaFuncSetAttribute(conv_char_fused,
                         cudaFuncAttributeMaxDynamicSharedMemorySize, SMEM_BYTES);
    conv_char_fused<<<dim3(NCHUNK, 2), THREADS, SMEM_BYTES>>>(
        input, emb, conv_w, conv_b, (float*)d_out);
}

// round 17
// speedup vs baseline: 1.0693x; 1.0154x over previous
#include <cuda_runtime.h>
#include <cuda_fp16.h>
#include <cstdint>

#define D_VOCAB 262
#define D_EMB   128
#define NTAP    5
#define CW      16
#define NSEQ    32768
#define NCHUNK  74
#define THREADS 512
#define NCTAS   (NCHUNK * 2)            // 148
// smem: table region [NTAP*D_VOCAB] rows of 64 ch (8 x uint4) = 167,680 B
#define SMEM_BYTES (NTAP * D_VOCAB * 32 * 4)
// uint4-unit stride of one tap plane: 262 rows * 8 uint4
#define TAPSTRIDE16 (D_VOCAB * 8)
// phase-1 weight scratch: ws[i][k*32+eL], row stride 164 floats (83,968 B)
#define WROW 164
// phase-1 emb scratch right after ws: 8 rows x 128 floats (4 KB)
#define EMB_OFF (D_EMB * WROW)

// fp16 contrib table: [tap][vocab][emb]
__device__ __align__(16) __half g_tab[NTAP * D_VOCAB * D_EMB];
// narrowed ids, PRE-MULTIPLIED BY 8 (uint4 row index); written phase 1,
// read phase 2 with PLAIN coherent loads only (__ldg illegal: same-launch).
__device__ __align__(16) unsigned short g_ids16[NSEQ * CW];
// grid-wide ticket barrier (monotonic across graph replays; no reset needed)
__device__ unsigned g_bar;

// ---------------------------------------------------------------------------
__device__ __forceinline__ uint4 h2add4(uint4 a, uint4 b) {
    uint4 r;
    *(__half2*)&r.x = __hadd2(*(const __half2*)&a.x, *(const __half2*)&b.x);
    *(__half2*)&r.y = __hadd2(*(const __half2*)&a.y, *(const __half2*)&b.y);
    *(__half2*)&r.z = __hadd2(*(const __half2*)&a.z, *(const __half2*)&b.z);
    *(__half2*)&r.w = __hadd2(*(const __half2*)&a.w, *(const __half2*)&b.w);
    return r;
}
__device__ __forceinline__ uint4 h2max4(uint4 a, uint4 b) {
    uint4 r;
    *(__half2*)&r.x = __hmax2(*(const __half2*)&a.x, *(const __half2*)&b.x);
    *(__half2*)&r.y = __hmax2(*(const __half2*)&a.y, *(const __half2*)&b.y);
    *(__half2*)&r.z = __hmax2(*(const __half2*)&a.z, *(const __half2*)&b.z);
    *(__half2*)&r.w = __hmax2(*(const __half2*)&a.w, *(const __half2*)&b.w);
    return r;
}

// ---------------------------------------------------------------------------
// Fused kernel. Grid (74, 2) = 148 CTAs, 164 KB smem -> 1 CTA/SM, all
// co-resident -> device-wide ticket barrier is safe.
// Phase 2 schedule (fixes warp tail imbalance): every warp runs EXACTLY
// 3 full 8-seq iterations (384 seqs, no guards needed: min chunk = 429),
// then one 4-seq half-iteration covers the 45-59 remaining seqs spread
// over ~12-15 warps. Slowest-warp cost 4.0 -> ~3.5 full iterations.
// ---------------------------------------------------------------------------
__global__ void __launch_bounds__(THREADS, 1)
conv_char_fused(const int* __restrict__ ids_raw,
                const float* __restrict__ emb,
                const float* __restrict__ conv_w,
                const float* __restrict__ conv_b,
                float* __restrict__ out) {
    extern __shared__ uint4 s_tab16[];
    float* ws = (float*)s_tab16;                 // phase-1 alias (88 KB)
    const int g = blockIdx.y;
    const int lane = threadIdx.x & 31;
    const int warp = threadIdx.x >> 5;
    const int l7 = lane & 7;
    const int q = lane >> 3;
    const int cta = blockIdx.y * NCHUNK + blockIdx.x;   // 0..147

    // Per-warp int64-vs-int32 detection (int64 ids < 262 -> zero high words).
    int s2;
    {
        int v = ids_raw[2 * lane + 1] | ids_raw[64 + 2 * lane + 1];
        s2 = (__ballot_sync(0xffffffffu, v != 0) == 0u) ? 1 : 0;
    }

    // ===== Phase 1a: build this CTA's slice of g_tab ======================
    {
        const int eg = cta & 3;            // 32-e group
        const int vg = cta >> 2;           // 8-v group (>=33 -> idle)
        const int e0 = eg * 32;
        const int v0 = vg * 8;

        const float4* __restrict__ cw4 = (const float4*)conv_w;
        for (int idx = threadIdx.x; idx < 32 * 160; idx += THREADS) {
            const int r = idx / 160;
            const int c = idx % 160;
            float4 w = __ldg(&cw4[(size_t)(e0 + r) * 160 + c]);
            const int j = 4 * c;
            ws[((j + 0) / 5) * WROW + ((j + 0) % 5) * 32 + r] = w.x;
            ws[((j + 1) / 5) * WROW + ((j + 1) % 5) * 32 + r] = w.y;
            ws[((j + 2) / 5) * WROW + ((j + 2) % 5) * 32 + r] = w.z;
            ws[((j + 3) / 5) * WROW + ((j + 3) % 5) * 32 + r] = w.w;
        }
        {
            const float4* __restrict__ embg = (const float4*)emb;
            float4* se4 = (float4*)(ws + EMB_OFF);
            if (threadIdx.x < 256) {
                const int vr = threadIdx.x >> 5;     // 0..7
                const int c = threadIdx.x & 31;
                const int vv = v0 + vr;
                se4[threadIdx.x] = (vv < D_VOCAB)
                    ? __ldg(&embg[vv * 32 + c])
                    : make_float4(0.f, 0.f, 0.f, 0.f);
            }
        }
        __syncthreads();

        if (threadIdx.x < 320 && v0 < D_VOCAB) {
            const int vh = threadIdx.x / 160;          // 0..1
            const int k = (threadIdx.x % 160) >> 5;    // 0..4
            const int eL = threadIdx.x & 31;
            const float* __restrict__ wcol = ws + k * 32 + eL;
            const float4* __restrict__ se4 = (const float4*)(ws + EMB_OFF);
            const int vb = vh * 4;

            float acc[4];
            #pragma unroll
            for (int v = 0; v < 4; ++v) acc[v] = 0.f;

            #pragma unroll 4
            for (int i4 = 0; i4 < 32; ++i4) {
                const float w0 = wcol[(i4 * 4 + 0) * WROW];
                const float w1 = wcol[(i4 * 4 + 1) * WROW];
                const float w2 = wcol[(i4 * 4 + 2) * WROW];
                const float w3 = wcol[(i4 * 4 + 3) * WROW];
                #pragma unroll
                for (int v = 0; v < 4; ++v) {
                    float4 em = se4[(vb + v) * 32 + i4];
                    acc[v] = fmaf(em.x, w0, acc[v]);
                    acc[v] = fmaf(em.y, w1, acc[v]);
                    acc[v] = fmaf(em.z, w2, acc[v]);
                    acc[v] = fmaf(em.w, w3, acc[v]);
                }
            }
            #pragma unroll
            for (int v = 0; v < 4; ++v) {
                const int vv = v0 + vb + v;
                if (vv < D_VOCAB)
                    g_tab[(k * D_VOCAB + vv) * D_EMB + e0 + eL] =
                        __float2half(acc[v]);
            }
        }
    }

    // ===== Phase 1b: narrow ids to int16, PRE-MULTIPLIED BY 8 =============
    {
        const int stride = NCTAS * THREADS;
        int i = cta * THREADS + threadIdx.x;
        if (s2) {
            const uint2* __restrict__ p2 = (const uint2*)ids_raw;
            for (; i < NSEQ * CW; i += stride)
                g_ids16[i] = (unsigned short)(__ldg(&p2[i]).x * 8u);
        } else {
            for (; i < NSEQ * CW; i += stride)
                g_ids16[i] = (unsigned short)(__ldg(&ids_raw[i]) * 8);
        }
    }

    // Release all stores, then grid barrier.
    __threadfence();
    __syncthreads();
    if (threadIdx.x == 0) {
        unsigned t = atomicAdd(&g_bar, 1u);
        unsigned target = (t / (unsigned)NCTAS) * (unsigned)NCTAS
                          + (unsigned)NCTAS;
        while (*(volatile unsigned*)&g_bar < target) { }
        __threadfence();
    }
    __syncthreads();

    // ===== Phase 2 =========================================================
    const int chunk = (NSEQ + NCHUNK - 1) / NCHUNK;  // 443
    const int base = blockIdx.x * chunk;
    const int end = min(base + chunk, NSEQ);         // chunk >= 429 always
    const int tbase = base + 384;                    // tail start

    // Prefetch iteration-0 ids for both groups (plain coherent loads).
    uint4 rawA[2], rawB[2];
    {
        const uint4* pA = (const uint4*)(g_ids16 + (size_t)(base + 8 * warp + q) * CW);
        const uint4* pB = (const uint4*)(g_ids16 + (size_t)(base + 8 * warp + 4 + q) * CW);
        rawA[0] = pA[0]; rawA[1] = pA[1];
        rawB[0] = pB[0]; rawB[1] = pB[1];
    }

    // Stage table slice from hot L2 (coalesced; plain loads).
    {
        const char* gb = (const char*)g_tab;
        for (int idx = threadIdx.x; idx < NTAP * D_VOCAB * 8; idx += THREADS) {
            int r = idx >> 3, c = idx & 7;
            s_tab16[idx] = *(const uint4*)(gb + (size_t)r * 256 + g * 128 + c * 16);
        }
    }
    __syncthreads();

    // ----- 3 full 8-seq iterations per warp (guards/clamps unnecessary) ----
    #pragma unroll
    for (int j = 0; j < 3; ++j) {
        const int n0 = base + 8 * warp + 128 * j;
        const int nselA = n0 + q;
        const int nselB = n0 + 4 + q;

        // Unpack 32 ids (pre-multiplied by 8) -> gather indices.
        int aA[CW], aB[CW];
        {
            const unsigned* wA = (const unsigned*)rawA;
            const unsigned* wB = (const unsigned*)rawB;
            #pragma unroll
            for (int jj = 0; jj < 8; ++jj) {
                unsigned a = wA[jj], b = wB[jj];
                aA[2 * jj]     = (int)(a & 0xFFFFu) + l7;
                aA[2 * jj + 1] = (int)(a >> 16) + l7;
                aB[2 * jj]     = (int)(b & 0xFFFFu) + l7;
                aB[2 * jj + 1] = (int)(b >> 16) + l7;
            }
        }

        // Prefetch next: j<2 -> next full iteration; j==2 -> tail group.
        if (j < 2) {
            const uint4* pA = (const uint4*)(g_ids16 + (size_t)(n0 + 128 + q) * CW);
            const uint4* pB = (const uint4*)(g_ids16 + (size_t)(n0 + 132 + q) * CW);
            rawA[0] = pA[0]; rawA[1] = pA[1];
            rawB[0] = pB[0]; rawB[1] = pB[1];
        } else {
            const int nt = min(tbase + 4 * warp + q, NSEQ - 1);
            const uint4* pA = (const uint4*)(g_ids16 + (size_t)nt * CW);
            rawA[0] = pA[0]; rawA[1] = pA[1];
        }

        // Interleaved dual-group t-loop.
        uint4 meA, moA, meB, moB;
        #pragma unroll
        for (int t = 0; t < CW; ++t) {
            const int klo = (t < 2) ? (2 - t) : 0;
            const int khi = (t > CW - 3) ? (CW + 1 - t) : NTAP - 1;
            const int nv = khi - klo + 1;

            uint4 sA[NTAP], sB[NTAP];
            #pragma unroll
            for (int k = 0; k < NTAP; ++k) {
                if (k < klo || k > khi) continue;
                sA[k] = s_tab16[k * TAPSTRIDE16 + aA[t + k - 2]];
                sB[k] = s_tab16[k * TAPSTRIDE16 + aB[t + k - 2]];
            }

            uint4 yA, yB;
            if (nv == 5) {
                yA = h2add4(h2add4(h2add4(sA[0], sA[1]), h2add4(sA[2], sA[3])), sA[4]);
                yB = h2add4(h2add4(h2add4(sB[0], sB[1]), h2add4(sB[2], sB[3])), sB[4]);
            } else if (nv == 4) {
                yA = h2add4(h2add4(sA[klo], sA[klo + 1]), h2add4(sA[klo + 2], sA[klo + 3]));
                yB = h2add4(h2add4(sB[klo], sB[klo + 1]), h2add4(sB[klo + 2], sB[klo + 3]));
            } else {
                yA = h2add4(h2add4(sA[klo], sA[klo + 1]), sA[klo + 2]);
                yB = h2add4(h2add4(sB[klo], sB[klo + 1]), sB[klo + 2]);
            }

            if (t == 0)      { meA = yA; meB = yB; }
            else if (t == 1) { moA = yA; moB = yB; }
            else if ((t & 1) == 0) { meA = h2max4(meA, yA); meB = h2max4(meB, yB); }
            else                   { moA = h2max4(moA, yA); moB = h2max4(moB, yB); }
        }
        const uint4 mA = h2max4(meA, moA);
        const uint4 mB = h2max4(meB, moB);

        const float4 bias0 = __ldg((const float4*)(conv_b + g * 64 + l7 * 8));
        const float4 bias1 = __ldg((const float4*)(conv_b + g * 64 + l7 * 8 + 4));

        {
            float2 c0 = __half22float2(*(const __half2*)&mA.x);
            float2 c1 = __half22float2(*(const __half2*)&mA.y);
            float2 c2 = __half22float2(*(const __half2*)&mA.z);
            float2 c3 = __half22float2(*(const __half2*)&mA.w);
            float4 o0, o1;
            o0.x = c0.x + bias0.x; o0.y = c0.y + bias0.y;
            o0.z = c1.x + bias0.z; o0.w = c1.y + bias0.w;
            o1.x = c2.x + bias1.x; o1.y = c2.y + bias1.y;
            o1.z = c3.x + bias1.z; o1.w = c3.y + bias1.w;
            float* op = out + (size_t)nselA * D_EMB + g * 64 + l7 * 8;
            *(float4*)op = o0;
            *(float4*)(op + 4) = o1;
        }
        {
            float2 c0 = __half22float2(*(const __half2*)&mB.x);
            float2 c1 = __half22float2(*(const __half2*)&mB.y);
            float2 c2 = __half22float2(*(const __half2*)&mB.z);
            float2 c3 = __half22float2(*(const __half2*)&mB.w);
            float4 o0, o1;
            o0.x = c0.x + bias0.x; o0.y = c0.y + bias0.y;
            o0.z = c1.x + bias0.z; o0.w = c1.y + bias0.w;
            o1.x = c2.x + bias1.x; o1.y = c2.y + bias1.y;
            o1.z = c3.x + bias1.z; o1.w = c3.y + bias1.w;
            float* op = out + (size_t)nselB * D_EMB + g * 64 + l7 * 8;
            *(float4*)op = o0;
            *(float4*)(op + 4) = o1;
        }
    }

    // ----- tail: one 4-seq half-iteration over [tbase, end) ---------------
    {
        const int nsel = tbase + 4 * warp + q;
        if (nsel < end) {
            int a[CW];
            {
                const unsigned* wA = (const unsigned*)rawA;
                #pragma unroll
                for (int jj = 0; jj < 8; ++jj) {
                    unsigned w = wA[jj];
                    a[2 * jj]     = (int)(w & 0xFFFFu) + l7;
                    a[2 * jj + 1] = (int)(w >> 16) + l7;
                }
            }

            uint4 me, mo;
            #pragma unroll
            for (int t = 0; t < CW; ++t) {
                const int klo = (t < 2) ? (2 - t) : 0;
                const int khi = (t > CW - 3) ? (CW + 1 - t) : NTAP - 1;
                const int nv = khi - klo + 1;

                uint4 s[NTAP];
                #pragma unroll
                for (int k = 0; k < NTAP; ++k) {
                    if (k < klo || k > khi) continue;
                    s[k] = s_tab16[k * TAPSTRIDE16 + a[t + k - 2]];
                }

                uint4 y;
                if (nv == 5) {
                    y = h2add4(h2add4(h2add4(s[0], s[1]), h2add4(s[2], s[3])), s[4]);
                } else if (nv == 4) {
                    y = h2add4(h2add4(s[klo], s[klo + 1]), h2add4(s[klo + 2], s[klo + 3]));
                } else {
                    y = h2add4(h2add4(s[klo], s[klo + 1]), s[klo + 2]);
                }

                if (t == 0)      me = y;
                else if (t == 1) mo = y;
                else if ((t & 1) == 0) me = h2max4(me, y);
                else                   mo = h2max4(mo, y);
            }
            const uint4 m = h2max4(me, mo);

            const float4 bias0 = __ldg((const float4*)(conv_b + g * 64 + l7 * 8));
            const float4 bias1 = __ldg((const float4*)(conv_b + g * 64 + l7 * 8 + 4));
            float2 c0 = __half22float2(*(const __half2*)&m.x);
            float2 c1 = __half22float2(*(const __half2*)&m.y);
            float2 c2 = __half22float2(*(const __half2*)&m.z);
            float2 c3 = __half22float2(*(const __half2*)&m.w);
            float4 o0, o1;
            o0.x = c0.x + bias0.x; o0.y = c0.y + bias0.y;
            o0.z = c1.x + bias0.z; o0.w = c1.y + bias0.w;
            o1.x = c2.x + bias1.x; o1.y = c2.y + bias1.y;
            o1.z = c3.x + bias1.z; o1.w = c3.y + bias1.w;
            float* op = out + (size_t)nsel * D_EMB + g * 64 + l7 * 8;
            *(float4*)op = o0;
            *(float4*)(op + 4) = o1;
        }
    }
}

// ---------------------------------------------------------------------------
extern "C" void kernel_launch(void* const* d_in, const int* in_sizes, int n_in,
                              void* d_out, int out_size) {
    const int* input = nullptr;
    const float* emb = nullptr;
    const float* conv_w = nullptr;
    const float* conv_b = nullptr;
    for (int i = 0; i < n_in; ++i) {
        switch (in_sizes[i]) {
            case 524288: input  = (const int*)d_in[i];   break;  // ids [128,256,16]
            case 33536:  emb    = (const float*)d_in[i]; break;  // [262,128]
            case 81920:  conv_w = (const float*)d_in[i]; break;  // [128,128,5]
            case 128:    conv_b = (const float*)d_in[i]; break;  // [128]
            default: break;  // lengths (32768) unused
        }
    }

    cudaFuncSetAttribute(conv_char_fused,
                         cudaFuncAttributeMaxDynamicSharedMemorySize, SMEM_BYTES);
    conv_char_fused<<<dim3(NCHUNK, 2), THREADS, SMEM_BYTES>>>(
        input, emb, conv_w, conv_b, (float*)d_out);
}